// round 14
// baseline (speedup 1.0000x reference)
#include <cuda_runtime.h>
#include <cmath>
#include <stdint.h>

#define AMAX 1024
#define WORDS 32
#define BMAX 2
#define CMAX 80
#define NK 8               // compact neighbor-list capacity (per box)
#define NBLK 148           // one block per SM, single uniform wave
#define ROWS (BMAX * AMAX) // 2048 global adjacency rows
#define RPB14 14           // ceil(2048/148)
#define ITEMS (BMAX * CMAX)
#define TOTF4 (ITEMS * (AMAX * 5 / 4))   // 204800 output float4
#define PER3 ((TOTF4 + NBLK - 1) / NBLK) // 1384 per block

// Scratch (static device arrays; no dynamic allocation allowed)
__device__ unsigned g_adjT[BMAX * WORDS * AMAX];          // fallback, degree>NK only
__device__ unsigned short g_nbr[ROWS * NK];               // compact neighbor lists
__device__ int g_ncnt[ROWS];                              // degrees
__device__ unsigned g_keep[ITEMS * WORDS];                // kept bitmask per item
__device__ int g_bar1;                                    // monotone epoch counters
__device__ int g_bar2;

__device__ __forceinline__ float4 regress_box(const float* __restrict__ reg,
                                              const float4* __restrict__ anchors4,
                                              int b, int t, int A, float Wf, float Hf) {
    float4 av = anchors4[t];
    float w = av.z - av.x, h = av.w - av.y;
    float cx = av.x + 0.5f * w, cy = av.y + 0.5f * h;
    const float* rb = reg + (size_t)b * 4 * A;
    float dx = rb[0 * A + t] * 0.1f;
    float dy = rb[1 * A + t] * 0.1f;
    float dw = rb[2 * A + t] * 0.2f;
    float dh = rb[3 * A + t] * 0.2f;
    float pcx = cx + dx * w, pcy = cy + dy * h;
    float pw = expf(dw) * w, ph = expf(dh) * h;
    float4 r;
    r.x = fmaxf(pcx - 0.5f * pw, 0.0f);
    r.y = fmaxf(pcy - 0.5f * ph, 0.0f);
    r.z = fminf(pcx + 0.5f * pw, Wf);
    r.w = fminf(pcy + 0.5f * ph, Hf);
    return r;
}

// Grid = 148 x 1024: one block per SM, uniform single wave (kills the
// 12-doubled-SM floor that pinned R9-R13 at 14.8us).
__global__ void __launch_bounds__(1024, 1) fused_kernel(
    const float* __restrict__ cls, const float* __restrict__ reg,
    const float* __restrict__ anchors, float* __restrict__ out,
    int A, int C, int nItems, float Wf, float Hf) {
    __shared__ float4 sbox[ROWS];                   // 32 KB: both batches' boxes
    __shared__ float sarea[ROWS];                   // 8 KB
    __shared__ float ssc[AMAX];                     // 4 KB (per-item scores)
    __shared__ unsigned sadj[RPB14 * 32];           // 1.8 KB ballot tile
    __shared__ volatile unsigned char sstate[AMAX]; // 0=undec, 1=dropped, 2=kept
    int bid = blockIdx.x;
    int i = threadIdx.x;
    int lane = i & 31, wid = i >> 5;
    int base = bid * RPB14;                         // first assigned global row

    // ---- Phase 0: regress ALL 2048 boxes locally (2 per thread) ----
    {
        float4 b0 = regress_box(reg, (const float4*)anchors, 0, i, A, Wf, Hf);
        float4 b1 = regress_box(reg, (const float4*)anchors, 1, i, A, Wf, Hf);
        sbox[i] = b0;          sbox[AMAX + i] = b1;
        sarea[i]       = (b0.z - b0.x) * (b0.w - b0.y);   // same expr: bit-identical
        sarea[AMAX + i] = (b1.z - b1.x) * (b1.w - b1.y);
    }
    __syncthreads();

    // ---- Phase 1a: warp wid = column-word wid; 14 global rows (both batches) ----
    {
        float4 bj0 = sbox[wid * 32 + lane];         // batch-0 column box
        float aj0  = sarea[wid * 32 + lane];
        float4 bj1 = sbox[AMAX + wid * 32 + lane];  // batch-1 column box
        float aj1  = sarea[AMAX + wid * 32 + lane];
        #pragma unroll
        for (int k = 0; k < RPB14; ++k) {
            int r = base + k;
            if (r >= ROWS) break;
            int rb = r >> 10;                       // row's batch
            float4 bj = rb ? bj1 : bj0;
            float ajj = rb ? aj1 : aj0;
            float4 b0 = sbox[r];                    // broadcast LDS
            float a0 = sarea[r];
            float i0 = fmaxf(fminf(b0.z, bj.z) - fmaxf(b0.x, bj.x), 0.0f) *
                       fmaxf(fminf(b0.w, bj.w) - fmaxf(b0.y, bj.y), 0.0f);
            // Conservative filter: IoU>0.5 => 3*inter > a+aj (real arithmetic);
            // 0.999 margin absorbs fp rounding. Exact decision via IEEE div
            // below -> bit-identical to reference.
            bool c0 = 3.0f * i0 >= 0.999f * (a0 + ajj);
            unsigned cb = __ballot_sync(0xffffffffu, c0);
            unsigned bal = 0;
            if (cb) {                               // rare path (warp-uniform)
                bool adj0 = c0 && (__fdiv_rn(i0, fmaxf((a0 + ajj) - i0, 1e-9f)) > 0.5f);
                bal = __ballot_sync(0xffffffffu, adj0);
            }
            if (lane == 0) sadj[k * 32 + wid] = bal;
        }
    }
    __syncthreads();

    // ---- Phase 1b: warps 0..13 emit their global row: lists + rare fallback ----
    if (wid < RPB14 && base + wid < ROWS) {
        int r = base + wid;
        int a = r & (AMAX - 1);
        unsigned m = sadj[wid * 32 + lane];
        if (lane == (a >> 5)) m &= ~(1u << (a & 31));        // drop self bit

        int cnt = __popc(m);
        int scan = cnt;
        #pragma unroll
        for (int d = 1; d < 32; d <<= 1) {
            int t = __shfl_up_sync(0xffffffffu, scan, d);
            if (lane >= d) scan += t;
        }
        int excl = scan - cnt;
        int tot = __shfl_sync(0xffffffffu, scan, 31);
        unsigned short* np = g_nbr + (size_t)r * NK;
        unsigned mm = m;
        int pos = excl;
        while (mm && pos < NK) {
            int t2 = __ffs(mm) - 1; mm &= mm - 1;
            np[pos++] = (unsigned short)(lane * 32 + t2);
        }
        if (lane == 0) g_ncnt[r] = tot;
        if (tot > NK)                                        // fallback rows only
            g_adjT[((size_t)(r >> 10) * WORDS + lane) * AMAX + a] = m;
    }
    __syncthreads();                  // block's rows written (CTA HB)

    // ---- Barrier 1: adjacency ready (148 signals; monotone epoch) ----
    if (i == 0) {
        __threadfence();
        int v = atomicAdd(&g_bar1, 1);
        int target = v - (v % NBLK) + NBLK;
        volatile int* dp = &g_bar1;
        while (*dp < target) __nanosleep(64);
        __threadfence();
    }
    __syncthreads();

    // ---- Phase 2: NMS items striped over blocks (only 12 blocks get a 2nd) ----
    int vlast = 0;
    for (int it = bid; it < nItems; it += NBLK) {
        int b = it / C;
        float s = cls[(size_t)it * AMAX + i];
        ssc[i] = s;
        sstate[i] = 0;
        __syncthreads();              // scores + state ready

        int tot = g_ncnt[b * AMAX + i];
        uint4 nv = *(const uint4*)&g_nbr[((size_t)b * AMAX + i) * NK];
        bool ovf = tot > NK;
        int cnt = ovf ? 0 : tot;

        unsigned short js[NK];
        int nh = 0;
        {
            unsigned words[4] = {nv.x, nv.y, nv.z, nv.w};
            #pragma unroll
            for (int k = 0; k < NK; ++k) {
                if (k < cnt) {
                    int j = (words[k >> 1] >> ((k & 1) * 16)) & 0xFFFF;
                    float sj = ssc[j];
                    if (sj > s || (sj == s && j < i)) js[nh++] = (unsigned short)j;
                }
            }
        }

        bool valid = s > 0.05f;
        bool mykept;
        if (!valid) { sstate[i] = 1; mykept = false; }
        else if (!ovf && nh == 0) { sstate[i] = 2; mykept = true; }
        else {
            // Async monotone dataflow; min-rank undecided always progresses.
            const unsigned* adjT = g_adjT + (size_t)b * WORDS * AMAX;
            for (;;) {
                bool sup = false, alld = true;
                if (!ovf) {
                    for (int k = 0; k < nh; ++k) {
                        unsigned char v = sstate[js[k]];
                        if (v == 2) { sup = true; break; }
                        if (v == 0) alld = false;
                    }
                } else {
                    #pragma unroll
                    for (int w = 0; w < WORDS; ++w) {
                        unsigned mm = adjT[w * AMAX + i];
                        while (mm) {
                            int bit = __ffs(mm) - 1; mm &= mm - 1;
                            int j = w * 32 + bit;
                            float sj = ssc[j];
                            if (sj > s || (sj == s && j < i)) {
                                unsigned char v = sstate[j];
                                if (v == 2) { sup = true; }
                                else if (v == 0) alld = false;
                            }
                        }
                        if (sup) break;
                    }
                }
                if (sup)  { sstate[i] = 1; mykept = false; break; }
                if (alld) { sstate[i] = 2; mykept = true;  break; }
            }
        }
        // Publish kept bits: warp wid owns word wid of this item.
        unsigned kb = __ballot_sync(0xffffffffu, mykept);
        if (lane == 0) g_keep[it * WORDS + wid] = kb;
        __syncthreads();              // all warps' keep-words stored (CTA HB)
        if (i == 0) {
            __threadfence();          // release g_keep for this item
            vlast = atomicAdd(&g_bar2, 1);
        }
        __syncthreads();              // before ssc/sstate reuse
    }

    // ---- Barrier 2: all 160 items decided (monotone epoch, nItems signals) ----
    if (i == 0) {
        int target = vlast - (vlast % nItems) + nItems;
        volatile int* dp = &g_bar2;
        while (*dp < target) __nanosleep(64);
        __threadfence();
    }
    __syncthreads();

    // ---- Phase 3: balanced coalesced output: 204800 float4 over 148 blocks ----
    const float* sboxf = (const float*)sbox;
    float4* out4 = (float4*)out;
    int start = bid * PER3;
    int end = start + PER3;
    if (end > TOTF4) end = TOTF4;
    for (int t = start + i; t < end; t += 1024) {
        int bc = t / 1280;                        // item
        int wi = t - bc * 1280;
        int bb = bc / C;                          // batch
        float4 v;
        float* vf = (float*)&v;
        #pragma unroll
        for (int kk = 0; kk < 4; ++kk) {
            int idx = wi * 4 + kk;
            int a = idx / 5;
            int f = idx - a * 5;
            bool kp = (g_keep[bc * WORDS + (a >> 5)] >> (a & 31)) & 1u;
            float x = 0.0f;
            if (kp) x = (f == 0) ? __ldg(&cls[(size_t)bc * AMAX + a])
                                 : sboxf[(bb * AMAX + a) * 4 + (f - 1)];
            vf[kk] = x;
        }
        out4[t] = v;
    }
}

extern "C" void kernel_launch(void* const* d_in, const int* in_sizes, int n_in,
                              void* d_out, int out_size) {
    // metadata order: image, cls_pred, reg_pred, anchors
    const float* cls = (const float*)d_in[1];
    const float* reg = (const float*)d_in[2];
    const float* anchors = (const float*)d_in[3];

    int A = in_sizes[3] / 4;                 // 1024
    int B = in_sizes[2] / (4 * A);           // 2
    int C = in_sizes[1] / (B * A);           // 80
    long long hw = (long long)in_sizes[0] / (3LL * B);
    int H = (int)(sqrt((double)hw) + 0.5);   // 2048 (image used for shape only)
    float Hf = (float)H, Wf = (float)H;

    fused_kernel<<<NBLK, 1024>>>(cls, reg, anchors, (float*)d_out,
                                 A, C, B * C, Wf, Hf);
}

// round 15
// speedup vs baseline: 1.2691x; 1.2691x over previous
#include <cuda_runtime.h>
#include <cmath>
#include <stdint.h>

#define AMAX 1024
#define WORDS 32
#define BMAX 2
#define CMAX 80
#define NK 8               // compact neighbor-list capacity (per box)
#define NBLK 148           // one block per SM, single uniform wave
#define ROWS (BMAX * AMAX) // 2048 global adjacency rows
#define RPB15 14           // ceil(2048/148)

// Scratch (static device arrays; no dynamic allocation allowed)
__device__ unsigned g_adjT[BMAX * WORDS * AMAX];          // fallback, degree>NK only
__device__ unsigned short g_nbr[ROWS * NK];               // compact neighbor lists
__device__ int g_ncnt[ROWS];                              // degrees
__device__ int g_bar1;                                    // monotone epoch counter

__device__ __forceinline__ float4 regress_box(const float* __restrict__ reg,
                                              const float4* __restrict__ anchors4,
                                              int b, int t, int A, float Wf, float Hf) {
    float4 av = anchors4[t];                       // one LDG.128
    float w = av.z - av.x, h = av.w - av.y;
    float cx = av.x + 0.5f * w, cy = av.y + 0.5f * h;
    const float* rb = reg + (size_t)b * 4 * A;
    float dx = rb[0 * A + t] * 0.1f;
    float dy = rb[1 * A + t] * 0.1f;
    float dw = rb[2 * A + t] * 0.2f;
    float dh = rb[3 * A + t] * 0.2f;
    float pcx = cx + dx * w, pcy = cy + dy * h;
    float pw = expf(dw) * w, ph = expf(dh) * h;
    float4 r;
    r.x = fmaxf(pcx - 0.5f * pw, 0.0f);
    r.y = fmaxf(pcy - 0.5f * ph, 0.0f);
    r.z = fminf(pcx + 0.5f * pw, Wf);
    r.w = fminf(pcy + 0.5f * ph, Hf);
    return r;
}

// Grid = 148 x 1024, 1 CTA/SM: uniform single wave. Phase 1 covers 14 of the
// 2048 global adjacency rows per block; items striped (12 blocks run a 2nd
// item at FULL SM rate). Phase 2 + output are the proven R12 code verbatim.
__global__ void __launch_bounds__(1024, 1) fused_kernel(
    const float* __restrict__ cls, const float* __restrict__ reg,
    const float* __restrict__ anchors, float* __restrict__ out,
    int A, int C, int nItems, float Wf, float Hf) {
    __shared__ float4 sbox[ROWS];                   // 32 KB: both batches
    __shared__ float sarea[ROWS];                   // 8 KB
    __shared__ float ssc[AMAX];                     // 4 KB (per-item scores)
    __shared__ unsigned sadj[RPB15 * 32];           // 1.8 KB ballot tile
    __shared__ volatile unsigned char sstate[AMAX]; // 0=undec, 1=dropped, 2=kept
    int bid = blockIdx.x;
    int i = threadIdx.x;
    int lane = i & 31, wid = i >> 5;
    int base = bid * RPB15;                         // first assigned global row

    // ---- Phase 0: regress all 2048 boxes (2/thread; MUFU volume is slack) ----
    {
        float4 b0 = regress_box(reg, (const float4*)anchors, 0, i, A, Wf, Hf);
        float4 b1 = regress_box(reg, (const float4*)anchors, 1, i, A, Wf, Hf);
        sbox[i] = b0;           sbox[AMAX + i] = b1;
        sarea[i]        = (b0.z - b0.x) * (b0.w - b0.y);  // same expr: bit-identical
        sarea[AMAX + i] = (b1.z - b1.x) * (b1.w - b1.y);
    }
    __syncthreads();

    // ---- Phase 1a: warp wid = column-word wid; 14 global rows ----
    {
        float4 bj0 = sbox[wid * 32 + lane];         // batch-0 column box
        float aj0  = sarea[wid * 32 + lane];
        float4 bj1 = sbox[AMAX + wid * 32 + lane];  // batch-1 column box
        float aj1  = sarea[AMAX + wid * 32 + lane];
        #pragma unroll
        for (int k = 0; k < RPB15; ++k) {
            int r = base + k;
            if (r >= ROWS) break;
            int rb = r >> 10;                       // row's batch
            float4 bj = rb ? bj1 : bj0;
            float ajj = rb ? aj1 : aj0;
            float4 b0 = sbox[r];                    // broadcast LDS
            float a0 = sarea[r];
            float i0 = fmaxf(fminf(b0.z, bj.z) - fmaxf(b0.x, bj.x), 0.0f) *
                       fmaxf(fminf(b0.w, bj.w) - fmaxf(b0.y, bj.y), 0.0f);
            // Conservative filter: IoU>0.5 => 3*inter > a+aj (real arithmetic);
            // 0.999 margin absorbs fp rounding. Exact decision via IEEE div
            // below -> bit-identical to reference.
            bool c0 = 3.0f * i0 >= 0.999f * (a0 + ajj);
            unsigned cb = __ballot_sync(0xffffffffu, c0);
            unsigned bal = 0;
            if (cb) {                               // rare path (warp-uniform)
                bool adj0 = c0 && (__fdiv_rn(i0, fmaxf((a0 + ajj) - i0, 1e-9f)) > 0.5f);
                bal = __ballot_sync(0xffffffffu, adj0);
            }
            if (lane == 0) sadj[k * 32 + wid] = bal;
        }
    }
    __syncthreads();

    // ---- Phase 1b: warps 0..13 emit their global row: lists + rare fallback ----
    if (wid < RPB15 && base + wid < ROWS) {
        int r = base + wid;
        int a = r & (AMAX - 1);
        unsigned m = sadj[wid * 32 + lane];
        if (lane == (a >> 5)) m &= ~(1u << (a & 31));        // drop self bit

        int cnt = __popc(m);
        int scan = cnt;
        #pragma unroll
        for (int d = 1; d < 32; d <<= 1) {
            int t = __shfl_up_sync(0xffffffffu, scan, d);
            if (lane >= d) scan += t;
        }
        int excl = scan - cnt;
        int tot = __shfl_sync(0xffffffffu, scan, 31);
        unsigned short* np = g_nbr + (size_t)r * NK;
        unsigned mm = m;
        int pos = excl;
        while (mm && pos < NK) {
            int t2 = __ffs(mm) - 1; mm &= mm - 1;
            np[pos++] = (unsigned short)(lane * 32 + t2);
        }
        if (lane == 0) g_ncnt[r] = tot;
        if (tot > NK)                                        // fallback rows only
            g_adjT[((size_t)(r >> 10) * WORDS + lane) * AMAX + a] = m;
    }
    __syncthreads();                  // block's rows written (CTA HB)

    // ---- Barrier 1: adjacency ready (148 signals; monotone epoch, replay-safe) ----
    if (i == 0) {
        __threadfence();              // release
        int v = atomicAdd(&g_bar1, 1);
        int target = v - (v % NBLK) + NBLK;
        volatile int* dp = &g_bar1;
        while (*dp < target) __nanosleep(64);
        __threadfence();              // acquire
    }
    __syncthreads();

    // ---- Phase 2: striped items; NMS + smem-sourced output per item (R12 code) ----
    for (int it = bid; it < nItems; it += NBLK) {
        int b = it / C;
        float s = cls[(size_t)it * AMAX + i];
        ssc[i] = s;
        sstate[i] = 0;
        __syncthreads();              // scores + state ready

        int total = g_ncnt[b * AMAX + i];
        uint4 nv = *(const uint4*)&g_nbr[((size_t)b * AMAX + i) * NK];
        bool ovf = total > NK;        // rare high-degree fallback
        int cnt = ovf ? 0 : total;

        // Higher-ranked neighbors (score desc, index asc) into registers.
        unsigned short js[NK];
        int nh = 0;
        {
            unsigned words[4] = {nv.x, nv.y, nv.z, nv.w};
            #pragma unroll
            for (int k = 0; k < NK; ++k) {
                if (k < cnt) {
                    int j = (words[k >> 1] >> ((k & 1) * 16)) & 0xFFFF;
                    float sj = ssc[j];
                    if (sj > s || (sj == s && j < i)) js[nh++] = (unsigned short)j;
                }
            }
        }

        bool valid = s > 0.05f;
        if (!valid) {
            sstate[i] = 1;            // never kept, never suppresses
        } else if (!ovf && nh == 0) {
            sstate[i] = 2;            // top of its chain: kept
        } else {
            // Async monotone dataflow: spin until all higher neighbors decided
            // or one kept. Min-rank undecided always progresses -> no deadlock.
            const unsigned* adjT = g_adjT + (size_t)b * WORDS * AMAX;
            for (;;) {
                bool sup = false, alld = true;
                if (!ovf) {
                    for (int k = 0; k < nh; ++k) {
                        unsigned char v = sstate[js[k]];
                        if (v == 2) { sup = true; break; }
                        if (v == 0) alld = false;
                    }
                } else {
                    #pragma unroll
                    for (int w = 0; w < WORDS; ++w) {
                        unsigned mm = adjT[w * AMAX + i];
                        while (mm) {
                            int bit = __ffs(mm) - 1; mm &= mm - 1;
                            int j = w * 32 + bit;
                            float sj = ssc[j];
                            if (sj > s || (sj == s && j < i)) {
                                unsigned char v = sstate[j];
                                if (v == 2) { sup = true; }
                                else if (v == 0) alld = false;
                            }
                        }
                        if (sup) break;
                    }
                }
                if (sup)  { sstate[i] = 1; break; }
                if (alld) { sstate[i] = 2; break; }
            }
        }
        __syncthreads();              // all decided; sstate stable

        // Coalesced float4 output from smem: 1280 float4 for this item.
        const float* sboxf = (const float*)(sbox + b * AMAX);
        float4* obase4 = (float4*)(out + (size_t)it * AMAX * 5);
        #pragma unroll
        for (int r = 0; r < 2; ++r) {
            int t = r * 1024 + i;
            if (t < (AMAX * 5) / 4) {
                float4 v;
                float* vf = (float*)&v;
                #pragma unroll
                for (int k = 0; k < 4; ++k) {
                    int idx = t * 4 + k;
                    int a = idx / 5;
                    int f = idx - a * 5;
                    float x = 0.0f;
                    if (sstate[a] == 2) x = (f == 0) ? ssc[a] : sboxf[a * 4 + (f - 1)];
                    vf[k] = x;
                }
                obase4[t] = v;
            }
        }
        __syncthreads();              // ssc/sstate reusable for next item
    }
}

extern "C" void kernel_launch(void* const* d_in, const int* in_sizes, int n_in,
                              void* d_out, int out_size) {
    // metadata order: image, cls_pred, reg_pred, anchors
    const float* cls = (const float*)d_in[1];
    const float* reg = (const float*)d_in[2];
    const float* anchors = (const float*)d_in[3];

    int A = in_sizes[3] / 4;                 // 1024
    int B = in_sizes[2] / (4 * A);           // 2
    int C = in_sizes[1] / (B * A);           // 80
    long long hw = (long long)in_sizes[0] / (3LL * B);
    int H = (int)(sqrt((double)hw) + 0.5);   // 2048 (image used for shape only)
    float Hf = (float)H, Wf = (float)H;

    fused_kernel<<<NBLK, 1024>>>(cls, reg, anchors, (float*)d_out,
                                 A, C, B * C, Wf, Hf);
}

// round 16
// speedup vs baseline: 1.4717x; 1.1597x over previous
#include <cuda_runtime.h>
#include <cmath>
#include <stdint.h>

#define AMAX 1024
#define WORDS 32
#define BMAX 2
#define CMAX 80
#define NK 8           // compact neighbor-list capacity (per box)
#define ARPB 16        // adjacency rows per producer block (64 blocks/batch)

// Scratch (static device arrays; no dynamic allocation allowed)
__device__ unsigned g_adjT[BMAX * WORDS * AMAX];          // fallback, degree>NK only
__device__ unsigned short g_nbr[BMAX * AMAX * NK];        // compact neighbor lists
__device__ int g_ncnt[BMAX * AMAX];                       // degrees

__device__ __forceinline__ float4 regress_box(const float* __restrict__ reg,
                                              const float4* __restrict__ anchors4,
                                              int b, int t, int A, float Wf, float Hf) {
    float4 av = anchors4[t];                       // one LDG.128
    float w = av.z - av.x, h = av.w - av.y;
    float cx = av.x + 0.5f * w, cy = av.y + 0.5f * h;
    const float* rb = reg + (size_t)b * 4 * A;
    float dx = rb[0 * A + t] * 0.1f;
    float dy = rb[1 * A + t] * 0.1f;
    float dw = rb[2 * A + t] * 0.2f;
    float dh = rb[3 * A + t] * 0.2f;
    float pcx = cx + dx * w, pcy = cy + dy * h;
    float pw = expf(dw) * w, ph = expf(dh) * h;
    float4 r;
    r.x = fmaxf(pcx - 0.5f * pw, 0.0f);
    r.y = fmaxf(pcy - 0.5f * ph, 0.0f);
    r.z = fminf(pcx + 0.5f * pw, Wf);
    r.w = fminf(pcy + 0.5f * ph, Hf);
    return r;
}

// Kernel A: adjacency producer. Grid = B*64 blocks x 1024. Block handles 16
// rows of its batch. Triggers PDL completion immediately so kernel B's staging
// overlaps with this kernel's execution.
__global__ void __launch_bounds__(1024, 2) adj_kernel(
    const float* __restrict__ reg, const float* __restrict__ anchors,
    int A, float Wf, float Hf) {
    __shared__ float4 sbox[AMAX];                   // 16 KB
    __shared__ float sarea[AMAX];                   // 4 KB
    __shared__ unsigned sadj[ARPB * 32];            // 2 KB ballot tile [row][word]
    cudaTriggerProgrammaticLaunchCompletion();      // let B launch + stage now
    int bid = blockIdx.x;
    int i = threadIdx.x;
    int lane = i & 31, wid = i >> 5;
    int b = bid >> 6;                               // 64 blocks per batch
    int base = (bid & 63) * ARPB;                   // first assigned row

    // Stage own batch's boxes: 1 regression per thread.
    float4 bx = regress_box(reg, (const float4*)anchors, b, i, A, Wf, Hf);
    sbox[i] = bx;
    sarea[i] = (bx.z - bx.x) * (bx.w - bx.y);       // same expr: bit-identical
    __syncthreads();

    // Phase a: warp wid = column-word wid; 16 rows serial.
    {
        float4 bj = sbox[wid * 32 + lane];          // loop-invariant column box
        float ajj = sarea[wid * 32 + lane];
        #pragma unroll
        for (int k = 0; k < ARPB; ++k) {
            int row = base + k;
            float4 b0 = sbox[row];                  // broadcast LDS
            float a0 = sarea[row];
            float i0 = fmaxf(fminf(b0.z, bj.z) - fmaxf(b0.x, bj.x), 0.0f) *
                       fmaxf(fminf(b0.w, bj.w) - fmaxf(b0.y, bj.y), 0.0f);
            // Conservative filter: IoU>0.5 => 3*inter > a+aj (real arithmetic);
            // 0.999 margin absorbs fp rounding. Exact decision via IEEE div
            // below -> bit-identical to reference.
            bool c0 = 3.0f * i0 >= 0.999f * (a0 + ajj);
            unsigned cb = __ballot_sync(0xffffffffu, c0);
            unsigned bal = 0;
            if (cb) {                               // rare path (warp-uniform)
                bool adj0 = c0 && (__fdiv_rn(i0, fmaxf((a0 + ajj) - i0, 1e-9f)) > 0.5f);
                bal = __ballot_sync(0xffffffffu, adj0);
            }
            if (lane == 0) sadj[k * 32 + wid] = bal;
        }
    }
    __syncthreads();

    // Phase b: warps 0..15 emit row (base+wid): lists + rare fallback.
    if (wid < ARPB) {
        int row = base + wid;
        unsigned m = sadj[wid * 32 + lane];
        if (lane == (row >> 5)) m &= ~(1u << (row & 31));    // drop self bit

        int cnt = __popc(m);
        int scan = cnt;
        #pragma unroll
        for (int d = 1; d < 32; d <<= 1) {
            int t = __shfl_up_sync(0xffffffffu, scan, d);
            if (lane >= d) scan += t;
        }
        int excl = scan - cnt;
        int tot = __shfl_sync(0xffffffffu, scan, 31);
        unsigned short* np = g_nbr + ((size_t)b * AMAX + row) * NK;
        unsigned mm = m;
        int pos = excl;
        while (mm && pos < NK) {
            int t2 = __ffs(mm) - 1; mm &= mm - 1;
            np[pos++] = (unsigned short)(lane * 32 + t2);
        }
        if (lane == 0) g_ncnt[b * AMAX + row] = tot;
        if (tot > NK)                                        // fallback rows only
            g_adjT[((size_t)b * WORDS + lane) * AMAX + row] = m;
    }
    // Kernel end = PDL dependency completion: all stores visible to B after
    // its cudaGridDependencySynchronize().
}

// Kernel B: NMS consumer. Grid = B*C blocks x 1024, one (b,c) each. Launched
// with ProgrammaticStreamSerialization: staging overlaps kernel A; the grid
// dependency sync replaces all software barriers.
__global__ void __launch_bounds__(1024, 2) nms_kernel(
    const float* __restrict__ cls, const float* __restrict__ reg,
    const float* __restrict__ anchors, float* __restrict__ out,
    int A, int C, float Wf, float Hf) {
    __shared__ float4 sbox[AMAX];                   // 16 KB
    __shared__ float ssc[AMAX];                     // 4 KB
    __shared__ volatile unsigned char sstate[AMAX]; // 0=undec, 1=dropped, 2=kept
    int bid = blockIdx.x;
    int i = threadIdx.x;
    int b = bid / C;

    // ---- Staging (overlaps kernel A's execution) ----
    float s = cls[(size_t)bid * AMAX + i];
    float4 mybx = regress_box(reg, (const float4*)anchors, b, i, A, Wf, Hf);
    sbox[i] = mybx;
    ssc[i] = s;
    sstate[i] = 0;
    __syncthreads();

    // ---- Hardware handoff: adjacency from kernel A now visible ----
    cudaGridDependencySynchronize();

    int total = g_ncnt[b * AMAX + i];
    uint4 nv = *(const uint4*)&g_nbr[((size_t)b * AMAX + i) * NK];
    bool ovf = total > NK;            // rare high-degree fallback
    int cnt = ovf ? 0 : total;

    // Higher-ranked neighbors (score desc, index asc) into registers.
    unsigned short js[NK];
    int nh = 0;
    {
        unsigned words[4] = {nv.x, nv.y, nv.z, nv.w};
        #pragma unroll
        for (int k = 0; k < NK; ++k) {
            if (k < cnt) {
                int j = (words[k >> 1] >> ((k & 1) * 16)) & 0xFFFF;
                float sj = ssc[j];
                if (sj > s || (sj == s && j < i)) js[nh++] = (unsigned short)j;
            }
        }
    }

    bool valid = s > 0.05f;
    if (!valid) {
        sstate[i] = 1;                // never kept, never suppresses
    } else if (!ovf && nh == 0) {
        sstate[i] = 2;                // top of its chain: kept
    } else {
        // Async monotone dataflow: spin until all higher neighbors decided or
        // one kept. Min-rank undecided always progresses -> no deadlock.
        const unsigned* adjT = g_adjT + (size_t)b * WORDS * AMAX;
        for (;;) {
            bool sup = false, alld = true;
            if (!ovf) {
                for (int k = 0; k < nh; ++k) {
                    unsigned char v = sstate[js[k]];
                    if (v == 2) { sup = true; break; }
                    if (v == 0) alld = false;
                }
            } else {
                #pragma unroll
                for (int w = 0; w < WORDS; ++w) {
                    unsigned mm = adjT[w * AMAX + i];
                    while (mm) {
                        int bit = __ffs(mm) - 1; mm &= mm - 1;
                        int j = w * 32 + bit;
                        float sj = ssc[j];
                        if (sj > s || (sj == s && j < i)) {
                            unsigned char v = sstate[j];
                            if (v == 2) { sup = true; }
                            else if (v == 0) alld = false;
                        }
                    }
                    if (sup) break;
                }
            }
            if (sup)  { sstate[i] = 1; break; }
            if (alld) { sstate[i] = 2; break; }
        }
    }
    __syncthreads();                  // all decided; sstate stable

    // Coalesced float4 output from smem: 1280 float4 for this item.
    const float* sboxf = (const float*)sbox;
    float4* obase4 = (float4*)(out + (size_t)bid * AMAX * 5);
    #pragma unroll
    for (int r = 0; r < 2; ++r) {
        int t = r * 1024 + i;
        if (t < (AMAX * 5) / 4) {
            float4 v;
            float* vf = (float*)&v;
            #pragma unroll
            for (int k = 0; k < 4; ++k) {
                int idx = t * 4 + k;
                int a = idx / 5;
                int f = idx - a * 5;
                float x = 0.0f;
                if (sstate[a] == 2) x = (f == 0) ? ssc[a] : sboxf[a * 4 + (f - 1)];
                vf[k] = x;
            }
            obase4[t] = v;
        }
    }
}

extern "C" void kernel_launch(void* const* d_in, const int* in_sizes, int n_in,
                              void* d_out, int out_size) {
    // metadata order: image, cls_pred, reg_pred, anchors
    const float* cls = (const float*)d_in[1];
    const float* reg = (const float*)d_in[2];
    const float* anchors = (const float*)d_in[3];

    int A = in_sizes[3] / 4;                 // 1024
    int B = in_sizes[2] / (4 * A);           // 2
    int C = in_sizes[1] / (B * A);           // 80
    long long hw = (long long)in_sizes[0] / (3LL * B);
    int H = (int)(sqrt((double)hw) + 0.5);   // 2048 (image used for shape only)
    float Hf = (float)H, Wf = (float)H;

    // Producer: adjacency (triggers PDL completion at start).
    adj_kernel<<<B * 64, 1024>>>(reg, anchors, A, Wf, Hf);

    // Consumer: launched with programmatic stream serialization so its
    // staging overlaps the producer; gridDependencySynchronize() inside
    // provides the hardware adjacency handoff.
    cudaLaunchConfig_t cfg = {};
    cfg.gridDim = dim3((unsigned)(B * C));
    cfg.blockDim = dim3(1024);
    cfg.dynamicSmemBytes = 0;
    cfg.stream = 0;
    cudaLaunchAttribute attrs[1];
    attrs[0].id = cudaLaunchAttributeProgrammaticStreamSerialization;
    attrs[0].val.programmaticStreamSerializationAllowed = 1;
    cfg.attrs = attrs;
    cfg.numAttrs = 1;
    cudaLaunchKernelEx(&cfg, nms_kernel, cls, reg, anchors, (float*)d_out,
                       A, C, Wf, Hf);
}

// round 17
// speedup vs baseline: 1.4754x; 1.0025x over previous
#include <cuda_runtime.h>
#include <cmath>
#include <stdint.h>

#define AMAX 1024
#define WORDS 32
#define BMAX 2
#define CMAX 80
#define NK 8           // compact neighbor-list capacity (per box)
#define ARPB 8         // adjacency rows per producer block (128 blocks/batch)

// Scratch (static device arrays; no dynamic allocation allowed)
__device__ unsigned g_adjT[BMAX * WORDS * AMAX];          // fallback, degree>NK only
__device__ unsigned short g_nbr[BMAX * AMAX * NK];        // compact neighbor lists
__device__ int g_ncnt[BMAX * AMAX];                       // degrees

__device__ __forceinline__ float4 regress_box(const float* __restrict__ reg,
                                              const float4* __restrict__ anchors4,
                                              int b, int t, int A, float Wf, float Hf) {
    float4 av = anchors4[t];                       // one LDG.128
    float w = av.z - av.x, h = av.w - av.y;
    float cx = av.x + 0.5f * w, cy = av.y + 0.5f * h;
    const float* rb = reg + (size_t)b * 4 * A;
    float dx = rb[0 * A + t] * 0.1f;
    float dy = rb[1 * A + t] * 0.1f;
    float dw = rb[2 * A + t] * 0.2f;
    float dh = rb[3 * A + t] * 0.2f;
    float pcx = cx + dx * w, pcy = cy + dy * h;
    float pw = expf(dw) * w, ph = expf(dh) * h;
    float4 r;
    r.x = fmaxf(pcx - 0.5f * pw, 0.0f);
    r.y = fmaxf(pcy - 0.5f * ph, 0.0f);
    r.z = fminf(pcx + 0.5f * pw, Wf);
    r.w = fminf(pcy + 0.5f * ph, Hf);
    return r;
}

// Kernel A: adjacency producer. Grid = B*128 blocks x 1024; 8 rows per block
// (2 per iteration). Triggers PDL completion at start so kernel B's staging
// overlaps this kernel's execution.
__global__ void __launch_bounds__(1024, 2) adj_kernel(
    const float* __restrict__ reg, const float* __restrict__ anchors,
    int A, float Wf, float Hf) {
    __shared__ float4 sbox[AMAX];                   // 16 KB
    __shared__ float sarea[AMAX];                   // 4 KB
    __shared__ unsigned sadj[ARPB * 32];            // 1 KB ballot tile [row][word]
    cudaTriggerProgrammaticLaunchCompletion();      // let B launch + stage now
    int bid = blockIdx.x;
    int i = threadIdx.x;
    int lane = i & 31, wid = i >> 5;
    int b = bid >> 7;                               // 128 blocks per batch
    int base = (bid & 127) * ARPB;                  // first assigned row

    // Stage own batch's boxes: 1 regression per thread.
    float4 bx = regress_box(reg, (const float4*)anchors, b, i, A, Wf, Hf);
    sbox[i] = bx;
    sarea[i] = (bx.z - bx.x) * (bx.w - bx.y);       // same expr: bit-identical
    __syncthreads();

    // Phase a: warp wid = column-word wid; 8 rows, 2 per iteration.
    {
        float4 bj = sbox[wid * 32 + lane];          // loop-invariant column box
        float ajj = sarea[wid * 32 + lane];
        #pragma unroll
        for (int k = 0; k < ARPB; k += 2) {
            int r0 = base + k;
            float4 b0 = sbox[r0];
            float4 b1 = sbox[r0 + 1];
            float a0 = sarea[r0];
            float a1 = sarea[r0 + 1];
            float i0 = fmaxf(fminf(b0.z, bj.z) - fmaxf(b0.x, bj.x), 0.0f) *
                       fmaxf(fminf(b0.w, bj.w) - fmaxf(b0.y, bj.y), 0.0f);
            float i1 = fmaxf(fminf(b1.z, bj.z) - fmaxf(b1.x, bj.x), 0.0f) *
                       fmaxf(fminf(b1.w, bj.w) - fmaxf(b1.y, bj.y), 0.0f);
            // Conservative filter: IoU>0.5 => 3*inter > a+aj (real arithmetic);
            // 0.999 margin absorbs fp rounding. Exact decision via IEEE div
            // below -> bit-identical to reference.
            bool c0 = 3.0f * i0 >= 0.999f * (a0 + ajj);
            bool c1 = 3.0f * i1 >= 0.999f * (a1 + ajj);
            unsigned cb = __ballot_sync(0xffffffffu, c0 || c1);
            unsigned bal0 = 0, bal1 = 0;
            if (cb) {                               // rare path (warp-uniform)
                bool adj0 = c0 && (__fdiv_rn(i0, fmaxf((a0 + ajj) - i0, 1e-9f)) > 0.5f);
                bool adj1 = c1 && (__fdiv_rn(i1, fmaxf((a1 + ajj) - i1, 1e-9f)) > 0.5f);
                bal0 = __ballot_sync(0xffffffffu, adj0);
                bal1 = __ballot_sync(0xffffffffu, adj1);
            }
            if (lane == 0) {
                sadj[k * 32 + wid] = bal0;
                sadj[(k + 1) * 32 + wid] = bal1;
            }
        }
    }
    __syncthreads();

    // Phase b: warps 0..7 emit row (base+wid): lists + rare fallback.
    if (wid < ARPB) {
        int row = base + wid;
        unsigned m = sadj[wid * 32 + lane];
        if (lane == (row >> 5)) m &= ~(1u << (row & 31));    // drop self bit

        int cnt = __popc(m);
        int scan = cnt;
        #pragma unroll
        for (int d = 1; d < 32; d <<= 1) {
            int t = __shfl_up_sync(0xffffffffu, scan, d);
            if (lane >= d) scan += t;
        }
        int excl = scan - cnt;
        int tot = __shfl_sync(0xffffffffu, scan, 31);
        unsigned short* np = g_nbr + ((size_t)b * AMAX + row) * NK;
        unsigned mm = m;
        int pos = excl;
        while (mm && pos < NK) {
            int t2 = __ffs(mm) - 1; mm &= mm - 1;
            np[pos++] = (unsigned short)(lane * 32 + t2);
        }
        if (lane == 0) g_ncnt[b * AMAX + row] = tot;
        if (tot > NK)                                        // fallback rows only
            g_adjT[((size_t)b * WORDS + lane) * AMAX + row] = m;
    }
    // Kernel end = PDL dependency completion: stores visible to B after its
    // cudaGridDependencySynchronize().
}

// Kernel B: NMS consumer (UNCHANGED from the 13.0us R16 version). Grid = B*C
// blocks x 1024, one (b,c) each, ProgrammaticStreamSerialization launch.
__global__ void __launch_bounds__(1024, 2) nms_kernel(
    const float* __restrict__ cls, const float* __restrict__ reg,
    const float* __restrict__ anchors, float* __restrict__ out,
    int A, int C, float Wf, float Hf) {
    __shared__ float4 sbox[AMAX];                   // 16 KB
    __shared__ float ssc[AMAX];                     // 4 KB
    __shared__ volatile unsigned char sstate[AMAX]; // 0=undec, 1=dropped, 2=kept
    int bid = blockIdx.x;
    int i = threadIdx.x;
    int b = bid / C;

    // ---- Staging (overlaps kernel A's execution) ----
    float s = cls[(size_t)bid * AMAX + i];
    float4 mybx = regress_box(reg, (const float4*)anchors, b, i, A, Wf, Hf);
    sbox[i] = mybx;
    ssc[i] = s;
    sstate[i] = 0;
    __syncthreads();

    // ---- Hardware handoff: adjacency from kernel A now visible ----
    cudaGridDependencySynchronize();

    int total = g_ncnt[b * AMAX + i];
    uint4 nv = *(const uint4*)&g_nbr[((size_t)b * AMAX + i) * NK];
    bool ovf = total > NK;            // rare high-degree fallback
    int cnt = ovf ? 0 : total;

    // Higher-ranked neighbors (score desc, index asc) into registers.
    unsigned short js[NK];
    int nh = 0;
    {
        unsigned words[4] = {nv.x, nv.y, nv.z, nv.w};
        #pragma unroll
        for (int k = 0; k < NK; ++k) {
            if (k < cnt) {
                int j = (words[k >> 1] >> ((k & 1) * 16)) & 0xFFFF;
                float sj = ssc[j];
                if (sj > s || (sj == s && j < i)) js[nh++] = (unsigned short)j;
            }
        }
    }

    bool valid = s > 0.05f;
    if (!valid) {
        sstate[i] = 1;                // never kept, never suppresses
    } else if (!ovf && nh == 0) {
        sstate[i] = 2;                // top of its chain: kept
    } else {
        // Async monotone dataflow: spin until all higher neighbors decided or
        // one kept. Min-rank undecided always progresses -> no deadlock.
        const unsigned* adjT = g_adjT + (size_t)b * WORDS * AMAX;
        for (;;) {
            bool sup = false, alld = true;
            if (!ovf) {
                for (int k = 0; k < nh; ++k) {
                    unsigned char v = sstate[js[k]];
                    if (v == 2) { sup = true; break; }
                    if (v == 0) alld = false;
                }
            } else {
                #pragma unroll
                for (int w = 0; w < WORDS; ++w) {
                    unsigned mm = adjT[w * AMAX + i];
                    while (mm) {
                        int bit = __ffs(mm) - 1; mm &= mm - 1;
                        int j = w * 32 + bit;
                        float sj = ssc[j];
                        if (sj > s || (sj == s && j < i)) {
                            unsigned char v = sstate[j];
                            if (v == 2) { sup = true; }
                            else if (v == 0) alld = false;
                        }
                    }
                    if (sup) break;
                }
            }
            if (sup)  { sstate[i] = 1; break; }
            if (alld) { sstate[i] = 2; break; }
        }
    }
    __syncthreads();                  // all decided; sstate stable

    // Coalesced float4 output from smem: 1280 float4 for this item.
    const float* sboxf = (const float*)sbox;
    float4* obase4 = (float4*)(out + (size_t)bid * AMAX * 5);
    #pragma unroll
    for (int r = 0; r < 2; ++r) {
        int t = r * 1024 + i;
        if (t < (AMAX * 5) / 4) {
            float4 v;
            float* vf = (float*)&v;
            #pragma unroll
            for (int k = 0; k < 4; ++k) {
                int idx = t * 4 + k;
                int a = idx / 5;
                int f = idx - a * 5;
                float x = 0.0f;
                if (sstate[a] == 2) x = (f == 0) ? ssc[a] : sboxf[a * 4 + (f - 1)];
                vf[k] = x;
            }
            obase4[t] = v;
        }
    }
}

extern "C" void kernel_launch(void* const* d_in, const int* in_sizes, int n_in,
                              void* d_out, int out_size) {
    // metadata order: image, cls_pred, reg_pred, anchors
    const float* cls = (const float*)d_in[1];
    const float* reg = (const float*)d_in[2];
    const float* anchors = (const float*)d_in[3];

    int A = in_sizes[3] / 4;                 // 1024
    int B = in_sizes[2] / (4 * A);           // 2
    int C = in_sizes[1] / (B * A);           // 80
    long long hw = (long long)in_sizes[0] / (3LL * B);
    int H = (int)(sqrt((double)hw) + 0.5);   // 2048 (image used for shape only)
    float Hf = (float)H, Wf = (float)H;

    // Producer: adjacency (PDL completion triggered at kernel start).
    adj_kernel<<<B * 128, 1024>>>(reg, anchors, A, Wf, Hf);

    // Consumer: programmatic stream serialization -> staging overlaps producer.
    cudaLaunchConfig_t cfg = {};
    cfg.gridDim = dim3((unsigned)(B * C));
    cfg.blockDim = dim3(1024);
    cfg.dynamicSmemBytes = 0;
    cfg.stream = 0;
    cudaLaunchAttribute attrs[1];
    attrs[0].id = cudaLaunchAttributeProgrammaticStreamSerialization;
    attrs[0].val.programmaticStreamSerializationAllowed = 1;
    cfg.attrs = attrs;
    cfg.numAttrs = 1;
    cudaLaunchKernelEx(&cfg, nms_kernel, cls, reg, anchors, (float*)d_out,
                       A, C, Wf, Hf);
}